// round 7
// baseline (speedup 1.0000x reference)
#include <cuda_runtime.h>
#include <cuda_bf16.h>
#include <cstdint>

constexpr int NB = 8, C = 64, HW = 4096;
constexpr int QT = 64;                 // q rows per CTA (16 per warp)
constexpr int KT = 64;                 // keys per iteration
constexpr int NKT = HW / KT;           // 64
constexpr float EPS_BN = 1e-5f;
constexpr float QSCALE = 0.125f * 1.4426950408889634f;  // (1/sqrt(64)) * log2(e)

__device__ __align__(256) float g_scale[C];
__device__ __align__(256) float g_shift[C];
__device__ __align__(256) float g_ps[512];
__device__ __align__(256) float g_pq[512];
__device__ unsigned int g_cnt;
__device__ __align__(256) __nv_bfloat16 g_Q[(size_t)NB * HW * C];   // [n,i,c] pre-scaled
__device__ __align__(256) __nv_bfloat16 g_Kb[(size_t)NB * HW * C];  // [n,j,c]
__device__ __align__(256) __nv_bfloat16 g_V[(size_t)NB * HW * C];   // [n,j,c]
__device__ __align__(256) float g_O[(size_t)NB * HW * C];           // [n,i,c]

// ---------- helpers ----------
__device__ __forceinline__ uint32_t smem_u32(const void* p) {
    uint32_t a;
    asm("{ .reg .u64 t; cvta.to.shared.u64 t, %1; cvt.u32.u64 %0, t; }" : "=r"(a) : "l"(p));
    return a;
}
__device__ __forceinline__ float ex2f(float x) {
    float y; asm("ex2.approx.ftz.f32 %0, %1;" : "=f"(y) : "f"(x)); return y;
}
__device__ __forceinline__ void cp_async16(uint32_t s, const void* g) {
    asm volatile("cp.async.cg.shared.global [%0], [%1], 16;" :: "r"(s), "l"(g));
}
__device__ __forceinline__ void cp_commit() { asm volatile("cp.async.commit_group;"); }

__device__ __forceinline__ void mma16816(float* d, const uint32_t* a, uint32_t b0, uint32_t b1) {
    asm volatile(
        "mma.sync.aligned.m16n8k16.row.col.f32.bf16.bf16.f32 "
        "{%0,%1,%2,%3}, {%4,%5,%6,%7}, {%8,%9}, {%0,%1,%2,%3};"
        : "+f"(d[0]), "+f"(d[1]), "+f"(d[2]), "+f"(d[3])
        : "r"(a[0]), "r"(a[1]), "r"(a[2]), "r"(a[3]), "r"(b0), "r"(b1));
}
__device__ __forceinline__ void ldsm4(uint32_t* r, uint32_t addr) {
    asm volatile("ldmatrix.sync.aligned.m8n8.x4.shared.b16 {%0,%1,%2,%3}, [%4];"
        : "=r"(r[0]), "=r"(r[1]), "=r"(r[2]), "=r"(r[3]) : "r"(addr));
}
__device__ __forceinline__ void ldsm4t(uint32_t* r, uint32_t addr) {
    asm volatile("ldmatrix.sync.aligned.m8n8.x4.trans.shared.b16 {%0,%1,%2,%3}, [%4];"
        : "=r"(r[0]), "=r"(r[1]), "=r"(r[2]), "=r"(r[3]) : "r"(addr));
}
__device__ __forceinline__ uint32_t packbf(float a, float b) {
    __nv_bfloat162 t = __floats2bfloat162_rn(a, b);
    return *reinterpret_cast<uint32_t*>(&t);
}

// ---------- kernel 1: BN stats, fused finalize (last block) ----------
__global__ __launch_bounds__(256) void bn_kernel(
    const float* __restrict__ x, const float* __restrict__ gamma,
    const float* __restrict__ beta) {
    int c = blockIdx.x >> 3, s = blockIdx.x & 7, t = threadIdx.x;
    const float* p = x + ((size_t)s * C + c) * HW;
    float sm = 0.f, sq = 0.f;
#pragma unroll
    for (int i = 0; i < HW / 256; i++) { float v = p[t + i * 256]; sm += v; sq += v * v; }
    __shared__ float rs[256], rq[256];
    __shared__ int isLast;
    rs[t] = sm; rq[t] = sq; __syncthreads();
    for (int o = 128; o > 0; o >>= 1) {
        if (t < o) { rs[t] += rs[t + o]; rq[t] += rq[t + o]; }
        __syncthreads();
    }
    if (t == 0) {
        g_ps[c * 8 + s] = rs[0]; g_pq[c * 8 + s] = rq[0];
        __threadfence();
        unsigned int prev = atomicAdd(&g_cnt, 1u);
        isLast = (prev == gridDim.x - 1);
    }
    __syncthreads();
    if (isLast) {
        __threadfence();
        if (t < C) {
            float sm2 = 0.f, sq2 = 0.f;
#pragma unroll
            for (int k = 0; k < 8; k++) { sm2 += g_ps[t * 8 + k]; sq2 += g_pq[t * 8 + k]; }
            float inv = 1.0f / (float)(NB * HW);
            float mean = sm2 * inv;
            float var = sq2 * inv - mean * mean;
            float sc = rsqrtf(var + EPS_BN) * gamma[t];
            g_scale[t] = sc;
            g_shift[t] = beta[t] - mean * sc;
        }
        if (t == 0) g_cnt = 0;   // reset for next graph replay
    }
}

// ---------- kernel 2: BN-apply + QKV via HMMA ----------
__global__ __launch_bounds__(128) void qkv_kernel(
    const float* __restrict__ x,
    const float* __restrict__ wq, const float* __restrict__ bq,
    const float* __restrict__ wk, const float* __restrict__ bk,
    const float* __restrict__ wv, const float* __restrict__ bv) {
    __shared__ __align__(16) char sX[128 * 128];
    __shared__ __align__(16) char sW[3][64 * 128];
    int t = threadIdx.x, wid = t >> 5, l = t & 31;
    int n = blockIdx.y;
    int p0 = blockIdx.x * 128;
    uint32_t sXa = smem_u32(sX);

    {
        const float* xb = x + (size_t)n * C * HW + p0 + t;
        int r7 = t & 7;
#pragma unroll
        for (int cp = 0; cp < 32; cp++) {
            int c0 = 2 * cp;
            float v0 = xb[(size_t)c0 * HW] * g_scale[c0] + g_shift[c0];
            float v1 = xb[(size_t)(c0 + 1) * HW] * g_scale[c0 + 1] + g_shift[c0 + 1];
            uint32_t pk = packbf(v0, v1);
            uint32_t off = ((uint32_t)(((c0 >> 3) ^ r7) << 4)) + (uint32_t)((c0 & 7) * 2);
            *reinterpret_cast<uint32_t*>(&((char*)sX)[t * 128 + off]) = pk;
        }
    }
    {
        const float* ws[3] = {wq, wk, wv};
#pragma unroll
        for (int w = 0; w < 3; w++) {
            const float* wp = ws[w];
#pragma unroll
            for (int i = 0; i < 16; i++) {
                int idx = t + i * 128;
                int o = idx >> 5, cp = idx & 31, c0 = 2 * cp;
                float2 wv2 = *reinterpret_cast<const float2*>(wp + o * 64 + c0);
                uint32_t pk = packbf(wv2.x, wv2.y);
                uint32_t off = ((uint32_t)(((c0 >> 3) ^ (o & 7)) << 4)) + (uint32_t)((c0 & 7) * 2);
                *reinterpret_cast<uint32_t*>(&sW[w][o * 128 + off]) = pk;
            }
        }
    }
    __syncthreads();

    uint32_t A[2][4][4];
    {
        int arow = (l & 7) + ((l >> 3) & 1) * 8;
        int l7 = l & 7;
#pragma unroll
        for (int mt2 = 0; mt2 < 2; mt2++) {
            int m0 = (wid * 2 + mt2) * 16;
#pragma unroll
            for (int kt = 0; kt < 4; kt++) {
                uint32_t chunk = (uint32_t)((kt * 2 + (l >> 4)) ^ l7);
                ldsm4(A[mt2][kt], sXa + (uint32_t)(m0 + arow) * 128 + (chunk << 4));
            }
        }
    }

    const float* biases[3] = {bq, bk, bv};
    __nv_bfloat16* outs[3] = {g_Q + (size_t)n * HW * C + (size_t)p0 * C,
                              g_Kb + (size_t)n * HW * C + (size_t)p0 * C,
                              g_V + (size_t)n * HW * C + (size_t)p0 * C};
    float scales[3] = {QSCALE, 1.f, 1.f};

    int brow = l & 7;
    uint32_t bx0 = (uint32_t)(((0 + (l >> 3)) ^ brow) << 4);
    uint32_t bx4 = (uint32_t)(((4 + (l >> 3)) ^ brow) << 4);

#pragma unroll
    for (int w = 0; w < 3; w++) {
        uint32_t sWa = smem_u32(sW[w]);
        float acc[2][8][4];
#pragma unroll
        for (int a = 0; a < 2; a++)
#pragma unroll
            for (int b = 0; b < 8; b++)
#pragma unroll
                for (int cc = 0; cc < 4; cc++) acc[a][b][cc] = 0.f;

#pragma unroll
        for (int nt = 0; nt < 8; nt++) {
            uint32_t base = sWa + (uint32_t)(nt * 8 + brow) * 128;
            uint32_t B[8];
            ldsm4(B, base + bx0);
            ldsm4(B + 4, base + bx4);
#pragma unroll
            for (int mt2 = 0; mt2 < 2; mt2++) {
                mma16816(acc[mt2][nt], A[mt2][0], B[0], B[1]);
                mma16816(acc[mt2][nt], A[mt2][1], B[2], B[3]);
                mma16816(acc[mt2][nt], A[mt2][2], B[4], B[5]);
                mma16816(acc[mt2][nt], A[mt2][3], B[6], B[7]);
            }
        }
        const float* bias = biases[w];
        float s = scales[w];
        __nv_bfloat16* op = outs[w];
#pragma unroll
        for (int nt = 0; nt < 8; nt++) {
            int col = nt * 8 + (l & 3) * 2;
            float2 bb = *reinterpret_cast<const float2*>(bias + col);
#pragma unroll
            for (int mt2 = 0; mt2 < 2; mt2++) {
                int row0 = (wid * 2 + mt2) * 16 + (l >> 2);
                uint32_t pk0 = packbf((acc[mt2][nt][0] + bb.x) * s, (acc[mt2][nt][1] + bb.y) * s);
                uint32_t pk1 = packbf((acc[mt2][nt][2] + bb.x) * s, (acc[mt2][nt][3] + bb.y) * s);
                *reinterpret_cast<uint32_t*>(op + (size_t)row0 * C + col) = pk0;
                *reinterpret_cast<uint32_t*>(op + (size_t)(row0 + 8) * C + col) = pk1;
            }
        }
    }
}

// ---------- kernel 3: flash attention (R5 configuration) ----------
constexpr int ROWB = 144;

__global__ __launch_bounds__(128) void attn_kernel() {
    __shared__ __align__(16) char sK[2][KT * ROWB];  // [key][ch]
    __shared__ __align__(16) char sV[2][KT * ROWB];  // [key][ch]
    int t = threadIdx.x, wid = t >> 5, lane = t & 31;
    int n = blockIdx.y, qt = blockIdx.x;
    int qrow0 = qt * QT + wid * 16;
    int m = lane >> 2;
    int qp = (lane & 3) * 2;

    const __nv_bfloat16* Kg = g_Kb + (size_t)n * HW * C;
    const __nv_bfloat16* Vg = g_V + (size_t)n * HW * C;

    uint32_t lds_off = (uint32_t)((lane & 7) * ROWB + (lane >> 3) * 16);
    uint32_t ldt_off = (uint32_t)(((lane & 7) + ((lane >> 3) & 1) * 8) * ROWB + (lane >> 4) * 16);
    uint32_t sKa = smem_u32(sK);
    uint32_t sVa = smem_u32(sV);

    uint32_t qa[4][4];
    {
        const __nv_bfloat16* Qb = g_Q + ((size_t)n * HW + qrow0) * C;
#pragma unroll
        for (int kb = 0; kb < 4; kb++) {
            qa[kb][0] = *(const uint32_t*)(Qb + (size_t)m * C + kb * 16 + qp);
            qa[kb][1] = *(const uint32_t*)(Qb + (size_t)(m + 8) * C + kb * 16 + qp);
            qa[kb][2] = *(const uint32_t*)(Qb + (size_t)m * C + kb * 16 + 8 + qp);
            qa[kb][3] = *(const uint32_t*)(Qb + (size_t)(m + 8) * C + kb * 16 + 8 + qp);
        }
    }

    float oacc[8][4];
#pragma unroll
    for (int i = 0; i < 8; i++)
#pragma unroll
        for (int j = 0; j < 4; j++) oacc[i][j] = 0.f;
    float lsum0 = 0.f, lsum1 = 0.f;

    auto prefetch = [&](int b, int kt) {
#pragma unroll
        for (int r = 0; r < 4; r++) {
            int ch = t + r * 128;
            int row = ch >> 3, col = ch & 7;
            cp_async16(sKa + (uint32_t)(b * KT * ROWB + row * ROWB + col * 16),
                       Kg + ((size_t)(kt * KT + row)) * C + col * 8);
            cp_async16(sVa + (uint32_t)(b * KT * ROWB + row * ROWB + col * 16),
                       Vg + ((size_t)(kt * KT + row)) * C + col * 8);
        }
        cp_commit();
    };

    prefetch(0, 0);

    for (int kt = 0; kt < NKT; kt++) {
        asm volatile("cp.async.wait_group 0;");
        __syncthreads();
        if (kt + 1 < NKT) prefetch((kt + 1) & 1, kt + 1);

        uint32_t kb_a = sKa + (uint32_t)((kt & 1) * KT * ROWB) + lds_off;
        uint32_t vb_a = sVa + (uint32_t)((kt & 1) * KT * ROWB) + ldt_off;

        float sacc[8][4];
#pragma unroll
        for (int nt = 0; nt < 8; nt++) {
#pragma unroll
            for (int j = 0; j < 4; j++) sacc[nt][j] = 0.f;
            uint32_t B[8];
            ldsm4(B, kb_a + nt * 8 * ROWB);
            ldsm4(B + 4, kb_a + nt * 8 * ROWB + 64);
            mma16816(sacc[nt], qa[0], B[0], B[1]);
            mma16816(sacc[nt], qa[1], B[2], B[3]);
            mma16816(sacc[nt], qa[2], B[4], B[5]);
            mma16816(sacc[nt], qa[3], B[6], B[7]);
        }

        uint32_t pa[4][4];
#pragma unroll
        for (int kc = 0; kc < 4; kc++) {
#pragma unroll
            for (int h = 0; h < 2; h++) {
                float e0 = ex2f(sacc[2 * kc + h][0]);
                float e1 = ex2f(sacc[2 * kc + h][1]);
                float e2 = ex2f(sacc[2 * kc + h][2]);
                float e3 = ex2f(sacc[2 * kc + h][3]);
                lsum0 += e0 + e1;
                lsum1 += e2 + e3;
                pa[kc][h * 2 + 0] = packbf(e0, e1);
                pa[kc][h * 2 + 1] = packbf(e2, e3);
            }
        }

#pragma unroll
        for (int np = 0; np < 4; np++) {
#pragma unroll
            for (int kc = 0; kc < 4; kc++) {
                uint32_t B[4];
                ldsm4t(B, vb_a + (uint32_t)(kc * 16 * ROWB + np * 32));
                mma16816(oacc[2 * np], pa[kc], B[0], B[1]);
                mma16816(oacc[2 * np + 1], pa[kc], B[2], B[3]);
            }
        }
    }

    lsum0 += __shfl_xor_sync(0xffffffffu, lsum0, 1);
    lsum0 += __shfl_xor_sync(0xffffffffu, lsum0, 2);
    lsum1 += __shfl_xor_sync(0xffffffffu, lsum1, 1);
    lsum1 += __shfl_xor_sync(0xffffffffu, lsum1, 2);
    float inv0 = 1.f / lsum0, inv1 = 1.f / lsum1;

    float* orow0 = g_O + ((size_t)n * HW + qrow0 + m) * C;
    float* orow1 = orow0 + 8 * C;
#pragma unroll
    for (int ct = 0; ct < 8; ct++) {
        int col = ct * 8 + qp;
        float2 v0 = make_float2(oacc[ct][0] * inv0, oacc[ct][1] * inv0);
        float2 v1 = make_float2(oacc[ct][2] * inv1, oacc[ct][3] * inv1);
        *reinterpret_cast<float2*>(orow0 + col) = v0;
        *reinterpret_cast<float2*>(orow1 + col) = v1;
    }
}

// ---------- kernel 4: output conv + residual (512 thr, 8 outputs/thread) ----------
constexpr int OP = 64;
__global__ __launch_bounds__(512) void out_kernel(
    const float* __restrict__ x, const float* __restrict__ wo,
    const float* __restrict__ bo, float* __restrict__ out) {
    __shared__ float sW[C * C];                 // transposed: sW[c*64+o]
    __shared__ __align__(16) float sv[C][OP];
    int t = threadIdx.x;
    int n = blockIdx.y;
    int p0 = blockIdx.x * OP;
    int g = t >> 6, pl = t & 63, p = p0 + pl;   // g in 0..7

    float xv[8];
    const float* xb = x + (size_t)n * C * HW + p;
#pragma unroll
    for (int o = 0; o < 8; o++) xv[o] = xb[(size_t)(g * 8 + o) * HW];

    for (int j = t; j < C * C; j += 512) sW[(j & 63) * C + (j >> 6)] = wo[j];
    {
        const float* Ob = g_O + (size_t)n * C * HW + p0;
        for (int j = t; j < C * 16; j += 512) {
            int c = j >> 4, w = j & 15;
            float4 v = *reinterpret_cast<const float4*>(Ob + (size_t)c * HW + w * 4);
            *reinterpret_cast<float4*>(&sv[c][w * 4]) = v;
        }
    }
    __syncthreads();

    float acc[8];
#pragma unroll
    for (int o = 0; o < 8; o++) acc[o] = bo[g * 8 + o];
#pragma unroll
    for (int c = 0; c < C; c++) {
        float v = sv[c][pl];
#pragma unroll
        for (int o = 0; o < 8; o++) acc[o] += sW[c * C + g * 8 + o] * v;
    }
    float* ob = out + (size_t)n * C * HW + p;
#pragma unroll
    for (int o = 0; o < 8; o++)
        ob[(size_t)(g * 8 + o) * HW] = acc[o] + xv[o];
}

extern "C" void kernel_launch(void* const* d_in, const int* in_sizes, int n_in,
                              void* d_out, int out_size) {
    const float* x     = (const float*)d_in[0];
    const float* gamma = (const float*)d_in[1];
    const float* beta  = (const float*)d_in[2];
    const float* wq    = (const float*)d_in[3];
    const float* bq    = (const float*)d_in[4];
    const float* wk    = (const float*)d_in[5];
    const float* bk    = (const float*)d_in[6];
    const float* wv    = (const float*)d_in[7];
    const float* bv    = (const float*)d_in[8];
    const float* wo    = (const float*)d_in[9];
    const float* bo    = (const float*)d_in[10];
    float* out = (float*)d_out;

    bn_kernel<<<512, 256>>>(x, gamma, beta);
    qkv_kernel<<<dim3(HW / 128, NB), 128>>>(x, wq, bq, wk, bk, wv, bv);
    attn_kernel<<<dim3(HW / QT, NB), 128>>>();
    out_kernel<<<dim3(HW / OP, NB), 512>>>(x, wo, bo, out);
}

// round 8
// speedup vs baseline: 1.5116x; 1.5116x over previous
#include <cuda_runtime.h>
#include <cuda_bf16.h>
#include <cstdint>

constexpr int NB = 8, C = 64, HW = 4096;
constexpr int QT = 64;                 // q rows per CTA
constexpr int KT = 64;                 // keys per iteration tile
constexpr int NKT = HW / KT;           // 64
constexpr float EPS_BN = 1e-5f;
constexpr float QSCALE = 0.125f * 1.4426950408889634f;  // (1/sqrt(64)) * log2(e)

__device__ __align__(256) float g_scale[C];
__device__ __align__(256) float g_shift[C];
__device__ __align__(256) float g_ps[512];
__device__ __align__(256) float g_pq[512];
__device__ __align__(256) __nv_bfloat16 g_Q[(size_t)NB * HW * C];   // [n,i,c] pre-scaled
__device__ __align__(256) __nv_bfloat16 g_Kb[(size_t)NB * HW * C];  // [n,j,c]
__device__ __align__(256) __nv_bfloat16 g_V[(size_t)NB * HW * C];   // [n,j,c]
__device__ __align__(256) float g_O[(size_t)NB * HW * C];           // [n,i,c]

// ---------- helpers ----------
__device__ __forceinline__ uint32_t smem_u32(const void* p) {
    uint32_t a;
    asm("{ .reg .u64 t; cvta.to.shared.u64 t, %1; cvt.u32.u64 %0, t; }" : "=r"(a) : "l"(p));
    return a;
}
__device__ __forceinline__ float ex2f(float x) {
    float y; asm("ex2.approx.ftz.f32 %0, %1;" : "=f"(y) : "f"(x)); return y;
}
__device__ __forceinline__ void cp_async16(uint32_t s, const void* g) {
    asm volatile("cp.async.cg.shared.global [%0], [%1], 16;" :: "r"(s), "l"(g));
}
__device__ __forceinline__ void cp_commit() { asm volatile("cp.async.commit_group;"); }

__device__ __forceinline__ void mma16816(float* d, const uint32_t* a, uint32_t b0, uint32_t b1) {
    asm volatile(
        "mma.sync.aligned.m16n8k16.row.col.f32.bf16.bf16.f32 "
        "{%0,%1,%2,%3}, {%4,%5,%6,%7}, {%8,%9}, {%0,%1,%2,%3};"
        : "+f"(d[0]), "+f"(d[1]), "+f"(d[2]), "+f"(d[3])
        : "r"(a[0]), "r"(a[1]), "r"(a[2]), "r"(a[3]), "r"(b0), "r"(b1));
}
__device__ __forceinline__ void ldsm4(uint32_t* r, uint32_t addr) {
    asm volatile("ldmatrix.sync.aligned.m8n8.x4.shared.b16 {%0,%1,%2,%3}, [%4];"
        : "=r"(r[0]), "=r"(r[1]), "=r"(r[2]), "=r"(r[3]) : "r"(addr));
}
__device__ __forceinline__ void ldsm4t(uint32_t* r, uint32_t addr) {
    asm volatile("ldmatrix.sync.aligned.m8n8.x4.trans.shared.b16 {%0,%1,%2,%3}, [%4];"
        : "=r"(r[0]), "=r"(r[1]), "=r"(r[2]), "=r"(r[3]) : "r"(addr));
}
__device__ __forceinline__ uint32_t packbf(float a, float b) {
    __nv_bfloat162 t = __floats2bfloat162_rn(a, b);
    return *reinterpret_cast<uint32_t*>(&t);
}

// ---------- kernel 1a: BN partial sums ----------
__global__ __launch_bounds__(256) void bn_part(const float* __restrict__ x) {
    int c = blockIdx.x >> 3, s = blockIdx.x & 7, t = threadIdx.x;
    const float* p = x + ((size_t)s * C + c) * HW;
    float sm = 0.f, sq = 0.f;
#pragma unroll
    for (int i = 0; i < HW / 256; i++) { float v = p[t + i * 256]; sm += v; sq += v * v; }
    __shared__ float rs[256], rq[256];
    rs[t] = sm; rq[t] = sq; __syncthreads();
    for (int o = 128; o > 0; o >>= 1) {
        if (t < o) { rs[t] += rs[t + o]; rq[t] += rq[t + o]; }
        __syncthreads();
    }
    if (t == 0) { g_ps[c * 8 + s] = rs[0]; g_pq[c * 8 + s] = rq[0]; }
}

// ---------- kernel 1b: BN finalize ----------
__global__ void bn_fin(const float* __restrict__ gamma, const float* __restrict__ beta) {
    int c = threadIdx.x;
    float sm = 0.f, sq = 0.f;
#pragma unroll
    for (int k = 0; k < 8; k++) { sm += g_ps[c * 8 + k]; sq += g_pq[c * 8 + k]; }
    float inv = 1.0f / (float)(NB * HW);
    float mean = sm * inv;
    float var = sq * inv - mean * mean;
    float sc = rsqrtf(var + EPS_BN) * gamma[c];
    g_scale[c] = sc;
    g_shift[c] = beta[c] - mean * sc;
}

// ---------- kernel 2: BN-apply + QKV via HMMA (R5, unchanged) ----------
__global__ __launch_bounds__(128) void qkv_kernel(
    const float* __restrict__ x,
    const float* __restrict__ wq, const float* __restrict__ bq,
    const float* __restrict__ wk, const float* __restrict__ bk,
    const float* __restrict__ wv, const float* __restrict__ bv) {
    __shared__ __align__(16) char sX[128 * 128];
    __shared__ __align__(16) char sW[3][64 * 128];
    int t = threadIdx.x, wid = t >> 5, l = t & 31;
    int n = blockIdx.y;
    int p0 = blockIdx.x * 128;
    uint32_t sXa = smem_u32(sX);

    {
        const float* xb = x + (size_t)n * C * HW + p0 + t;
        int r7 = t & 7;
#pragma unroll
        for (int cp = 0; cp < 32; cp++) {
            int c0 = 2 * cp;
            float v0 = xb[(size_t)c0 * HW] * g_scale[c0] + g_shift[c0];
            float v1 = xb[(size_t)(c0 + 1) * HW] * g_scale[c0 + 1] + g_shift[c0 + 1];
            uint32_t pk = packbf(v0, v1);
            uint32_t off = ((uint32_t)(((c0 >> 3) ^ r7) << 4)) + (uint32_t)((c0 & 7) * 2);
            *reinterpret_cast<uint32_t*>(&((char*)sX)[t * 128 + off]) = pk;
        }
    }
    {
        const float* ws[3] = {wq, wk, wv};
#pragma unroll
        for (int w = 0; w < 3; w++) {
            const float* wp = ws[w];
#pragma unroll
            for (int i = 0; i < 16; i++) {
                int idx = t + i * 128;
                int o = idx >> 5, cp = idx & 31, c0 = 2 * cp;
                float2 wv2 = *reinterpret_cast<const float2*>(wp + o * 64 + c0);
                uint32_t pk = packbf(wv2.x, wv2.y);
                uint32_t off = ((uint32_t)(((c0 >> 3) ^ (o & 7)) << 4)) + (uint32_t)((c0 & 7) * 2);
                *reinterpret_cast<uint32_t*>(&sW[w][o * 128 + off]) = pk;
            }
        }
    }
    __syncthreads();

    uint32_t A[2][4][4];
    {
        int arow = (l & 7) + ((l >> 3) & 1) * 8;
        int l7 = l & 7;
#pragma unroll
        for (int mt2 = 0; mt2 < 2; mt2++) {
            int m0 = (wid * 2 + mt2) * 16;
#pragma unroll
            for (int kt = 0; kt < 4; kt++) {
                uint32_t chunk = (uint32_t)((kt * 2 + (l >> 4)) ^ l7);
                ldsm4(A[mt2][kt], sXa + (uint32_t)(m0 + arow) * 128 + (chunk << 4));
            }
        }
    }

    const float* biases[3] = {bq, bk, bv};
    __nv_bfloat16* outs[3] = {g_Q + (size_t)n * HW * C + (size_t)p0 * C,
                              g_Kb + (size_t)n * HW * C + (size_t)p0 * C,
                              g_V + (size_t)n * HW * C + (size_t)p0 * C};
    float scales[3] = {QSCALE, 1.f, 1.f};

    int brow = l & 7;
    uint32_t bx0 = (uint32_t)(((0 + (l >> 3)) ^ brow) << 4);
    uint32_t bx4 = (uint32_t)(((4 + (l >> 3)) ^ brow) << 4);

#pragma unroll
    for (int w = 0; w < 3; w++) {
        uint32_t sWa = smem_u32(sW[w]);
        float acc[2][8][4];
#pragma unroll
        for (int a = 0; a < 2; a++)
#pragma unroll
            for (int b = 0; b < 8; b++)
#pragma unroll
                for (int cc = 0; cc < 4; cc++) acc[a][b][cc] = 0.f;

#pragma unroll
        for (int nt = 0; nt < 8; nt++) {
            uint32_t base = sWa + (uint32_t)(nt * 8 + brow) * 128;
            uint32_t B[8];
            ldsm4(B, base + bx0);
            ldsm4(B + 4, base + bx4);
#pragma unroll
            for (int mt2 = 0; mt2 < 2; mt2++) {
                mma16816(acc[mt2][nt], A[mt2][0], B[0], B[1]);
                mma16816(acc[mt2][nt], A[mt2][1], B[2], B[3]);
                mma16816(acc[mt2][nt], A[mt2][2], B[4], B[5]);
                mma16816(acc[mt2][nt], A[mt2][3], B[6], B[7]);
            }
        }
        const float* bias = biases[w];
        float s = scales[w];
        __nv_bfloat16* op = outs[w];
#pragma unroll
        for (int nt = 0; nt < 8; nt++) {
            int col = nt * 8 + (l & 3) * 2;
            float2 bb = *reinterpret_cast<const float2*>(bias + col);
#pragma unroll
            for (int mt2 = 0; mt2 < 2; mt2++) {
                int row0 = (wid * 2 + mt2) * 16 + (l >> 2);
                uint32_t pk0 = packbf((acc[mt2][nt][0] + bb.x) * s, (acc[mt2][nt][1] + bb.y) * s);
                uint32_t pk1 = packbf((acc[mt2][nt][2] + bb.x) * s, (acc[mt2][nt][3] + bb.y) * s);
                *reinterpret_cast<uint32_t*>(op + (size_t)row0 * C + col) = pk0;
                *reinterpret_cast<uint32_t*>(op + (size_t)(row0 + 8) * C + col) = pk1;
            }
        }
    }
}

// ---------- kernel 3: flash attention, 8 warps = 4 row-groups x 2 key-halves ----------
constexpr int ROWB = 144;

__global__ __launch_bounds__(256, 3) void attn_kernel() {
    __shared__ __align__(16) char sK[2][KT * ROWB];  // [key][ch]
    __shared__ __align__(16) char sV[2][KT * ROWB];  // [key][ch]
    int t = threadIdx.x, wid = t >> 5, lane = t & 31;
    int n = blockIdx.y, qt = blockIdx.x;
    int r = wid >> 1, h = wid & 1;         // row-group (0..3), key-half (0..1)
    int qrow0 = qt * QT + r * 16;
    int m = lane >> 2;
    int qp = (lane & 3) * 2;

    const __nv_bfloat16* Kg = g_Kb + (size_t)n * HW * C;
    const __nv_bfloat16* Vg = g_V + (size_t)n * HW * C;

    uint32_t lds_off = (uint32_t)((lane & 7) * ROWB + (lane >> 3) * 16);
    uint32_t ldt_off = (uint32_t)(((lane & 7) + ((lane >> 3) & 1) * 8) * ROWB + (lane >> 4) * 16);
    uint32_t sKa = smem_u32(sK);
    uint32_t sVa = smem_u32(sV);

    // Q fragments (loop-invariant)
    uint32_t qa[4][4];
    {
        const __nv_bfloat16* Qb = g_Q + ((size_t)n * HW + qrow0) * C;
#pragma unroll
        for (int kb = 0; kb < 4; kb++) {
            qa[kb][0] = *(const uint32_t*)(Qb + (size_t)m * C + kb * 16 + qp);
            qa[kb][1] = *(const uint32_t*)(Qb + (size_t)(m + 8) * C + kb * 16 + qp);
            qa[kb][2] = *(const uint32_t*)(Qb + (size_t)m * C + kb * 16 + 8 + qp);
            qa[kb][3] = *(const uint32_t*)(Qb + (size_t)(m + 8) * C + kb * 16 + 8 + qp);
        }
    }

    float oacc[8][4];
#pragma unroll
    for (int i = 0; i < 8; i++)
#pragma unroll
        for (int j = 0; j < 4; j++) oacc[i][j] = 0.f;
    float lsum0 = 0.f, lsum1 = 0.f;

    auto prefetch = [&](int b, int kt) {
#pragma unroll
        for (int rr = 0; rr < 2; rr++) {
            int ch = t + rr * 256;          // 0..511 : 16B chunks
            int row = ch >> 3, col = ch & 7;
            cp_async16(sKa + (uint32_t)(b * KT * ROWB + row * ROWB + col * 16),
                       Kg + ((size_t)(kt * KT + row)) * C + col * 8);
            cp_async16(sVa + (uint32_t)(b * KT * ROWB + row * ROWB + col * 16),
                       Vg + ((size_t)(kt * KT + row)) * C + col * 8);
        }
        cp_commit();
    };

    prefetch(0, 0);

    uint32_t kh_row = (uint32_t)(h * 32) * ROWB;   // this warp's 32-key slice

    for (int kt = 0; kt < NKT; kt++) {
        asm volatile("cp.async.wait_group 0;");
        __syncthreads();
        if (kt + 1 < NKT) prefetch((kt + 1) & 1, kt + 1);

        uint32_t kb_a = sKa + (uint32_t)((kt & 1) * KT * ROWB) + kh_row + lds_off;
        uint32_t vb_a = sVa + (uint32_t)((kt & 1) * KT * ROWB) + kh_row + ldt_off;

        // MMA1: S[16 x 32keys] = Q * K^T
        float sacc[4][4];
#pragma unroll
        for (int nt = 0; nt < 4; nt++) {
#pragma unroll
            for (int j = 0; j < 4; j++) sacc[nt][j] = 0.f;
            uint32_t B[8];
            ldsm4(B, kb_a + nt * 8 * ROWB);
            ldsm4(B + 4, kb_a + nt * 8 * ROWB + 64);
            mma16816(sacc[nt], qa[0], B[0], B[1]);
            mma16816(sacc[nt], qa[1], B[2], B[3]);
            mma16816(sacc[nt], qa[2], B[4], B[5]);
            mma16816(sacc[nt], qa[3], B[6], B[7]);
        }

        // exp2 + rowsum + pack
        uint32_t pa[2][4];
#pragma unroll
        for (int kc = 0; kc < 2; kc++) {
#pragma unroll
            for (int hh = 0; hh < 2; hh++) {
                float e0 = ex2f(sacc[2 * kc + hh][0]);
                float e1 = ex2f(sacc[2 * kc + hh][1]);
                float e2 = ex2f(sacc[2 * kc + hh][2]);
                float e3 = ex2f(sacc[2 * kc + hh][3]);
                lsum0 += e0 + e1;
                lsum1 += e2 + e3;
                pa[kc][hh * 2 + 0] = packbf(e0, e1);
                pa[kc][hh * 2 + 1] = packbf(e2, e3);
            }
        }

        // MMA2: O[16 x 64ch] += P * V (partial over this warp's 32 keys)
#pragma unroll
        for (int np = 0; np < 4; np++) {
#pragma unroll
            for (int kc = 0; kc < 2; kc++) {
                uint32_t B[4];
                ldsm4t(B, vb_a + (uint32_t)(kc * 16 * ROWB + np * 32));
                mma16816(oacc[2 * np], pa[kc], B[0], B[1]);
                mma16816(oacc[2 * np + 1], pa[kc], B[2], B[3]);
            }
        }
    }

    // quad-reduce row sums
    lsum0 += __shfl_xor_sync(0xffffffffu, lsum0, 1);
    lsum0 += __shfl_xor_sync(0xffffffffu, lsum0, 2);
    lsum1 += __shfl_xor_sync(0xffffffffu, lsum1, 1);
    lsum1 += __shfl_xor_sync(0xffffffffu, lsum1, 2);

    // cross-warp (key-half) reduction via smem, reusing sK/sV
    __syncthreads();
    float* sO = reinterpret_cast<float*>(sK);   // [64][64] floats = 16 KB (< 18.4 KB)
    float* sL = reinterpret_cast<float*>(sV);   // [64]
    int row0 = r * 16 + m;                      // 0..63
    if (h == 1) {
#pragma unroll
        for (int ct = 0; ct < 8; ct++) {
            int col = ct * 8 + qp;
            *reinterpret_cast<float2*>(sO + row0 * 64 + col) = make_float2(oacc[ct][0], oacc[ct][1]);
            *reinterpret_cast<float2*>(sO + (row0 + 8) * 64 + col) = make_float2(oacc[ct][2], oacc[ct][3]);
        }
        if ((lane & 3) == 0) { sL[row0] = lsum0; sL[row0 + 8] = lsum1; }
    }
    __syncthreads();
    if (h == 0) {
        float inv0 = 1.f / (lsum0 + sL[row0]);
        float inv1 = 1.f / (lsum1 + sL[row0 + 8]);
        float* orow0 = g_O + ((size_t)n * HW + qrow0 + m) * C;
        float* orow1 = orow0 + 8 * C;
#pragma unroll
        for (int ct = 0; ct < 8; ct++) {
            int col = ct * 8 + qp;
            float2 p0 = *reinterpret_cast<const float2*>(sO + row0 * 64 + col);
            float2 p1 = *reinterpret_cast<const float2*>(sO + (row0 + 8) * 64 + col);
            float2 v0 = make_float2((oacc[ct][0] + p0.x) * inv0, (oacc[ct][1] + p0.y) * inv0);
            float2 v1 = make_float2((oacc[ct][2] + p1.x) * inv1, (oacc[ct][3] + p1.y) * inv1);
            *reinterpret_cast<float2*>(orow0 + col) = v0;
            *reinterpret_cast<float2*>(orow1 + col) = v1;
        }
    }
}

// ---------- kernel 4: output conv + residual (R5 version, unchanged) ----------
constexpr int OP = 64;
__global__ __launch_bounds__(256) void out_kernel(
    const float* __restrict__ x, const float* __restrict__ wo,
    const float* __restrict__ bo, float* __restrict__ out) {
    __shared__ float sW[C * C];
    __shared__ __align__(16) float sv[C][OP];
    int t = threadIdx.x;
    int n = blockIdx.y;
    int p0 = blockIdx.x * OP;
    int g = t >> 6, pl = t & 63, p = p0 + pl;

    float xv[16];
    const float* xb = x + (size_t)n * C * HW + p;
#pragma unroll
    for (int o = 0; o < 16; o++) xv[o] = xb[(size_t)(g * 16 + o) * HW];

    for (int j = t; j < C * C; j += 256) sW[(j & 63) * C + (j >> 6)] = wo[j];
    {
        const float* Ob = g_O + (size_t)n * C * HW + p0;
        for (int j = t; j < C * 16; j += 256) {
            int c = j >> 4, w = j & 15;
            float4 v = *reinterpret_cast<const float4*>(Ob + (size_t)c * HW + w * 4);
            *reinterpret_cast<float4*>(&sv[c][w * 4]) = v;
        }
    }
    __syncthreads();

    float acc[16];
#pragma unroll
    for (int o = 0; o < 16; o++) acc[o] = bo[g * 16 + o];
#pragma unroll
    for (int c = 0; c < C; c++) {
        float v = sv[c][pl];
#pragma unroll
        for (int o = 0; o < 16; o++) acc[o] += sW[c * C + g * 16 + o] * v;
    }
    float* ob = out + (size_t)n * C * HW + p;
#pragma unroll
    for (int o = 0; o < 16; o++)
        ob[(size_t)(g * 16 + o) * HW] = acc[o] + xv[o];
}

extern "C" void kernel_launch(void* const* d_in, const int* in_sizes, int n_in,
                              void* d_out, int out_size) {
    const float* x     = (const float*)d_in[0];
    const float* gamma = (const float*)d_in[1];
    const float* beta  = (const float*)d_in[2];
    const float* wq    = (const float*)d_in[3];
    const float* bq    = (const float*)d_in[4];
    const float* wk    = (const float*)d_in[5];
    const float* bk    = (const float*)d_in[6];
    const float* wv    = (const float*)d_in[7];
    const float* bv    = (const float*)d_in[8];
    const float* wo    = (const float*)d_in[9];
    const float* bo    = (const float*)d_in[10];
    float* out = (float*)d_out;

    bn_part<<<512, 256>>>(x);
    bn_fin<<<1, 64>>>(gamma, beta);
    qkv_kernel<<<dim3(HW / 128, NB), 128>>>(x, wq, bq, wk, bk, wv, bv);
    attn_kernel<<<dim3(HW / QT, NB), 256>>>();
    out_kernel<<<dim3(HW / OP, NB), 256>>>(x, wo, bo, out);
}

// round 9
// speedup vs baseline: 1.7292x; 1.1440x over previous
#include <cuda_runtime.h>
#include <cuda_bf16.h>
#include <cstdint>

constexpr int NB = 8, C = 64, HW = 4096;
constexpr int QT = 128;                // q rows per CTA (32 per warp, 2 mtiles)
constexpr int KT = 64;                 // keys per iteration tile
constexpr int NKT = HW / KT;           // 64
constexpr float EPS_BN = 1e-5f;
constexpr float QSCALE = 0.125f * 1.4426950408889634f;  // (1/sqrt(64)) * log2(e)

__device__ __align__(256) float g_scale[C];
__device__ __align__(256) float g_shift[C];
__device__ __align__(256) float g_ps[512];
__device__ __align__(256) float g_pq[512];
__device__ __align__(256) __nv_bfloat16 g_Q[(size_t)NB * HW * C];   // [n,i,c] pre-scaled
__device__ __align__(256) __nv_bfloat16 g_Kb[(size_t)NB * HW * C];  // [n,j,c]
__device__ __align__(256) __nv_bfloat16 g_V[(size_t)NB * HW * C];   // [n,j,c]
__device__ __align__(256) float g_O[(size_t)NB * HW * C];           // [n,i,c]

// ---------- helpers ----------
__device__ __forceinline__ uint32_t smem_u32(const void* p) {
    uint32_t a;
    asm("{ .reg .u64 t; cvta.to.shared.u64 t, %1; cvt.u32.u64 %0, t; }" : "=r"(a) : "l"(p));
    return a;
}
__device__ __forceinline__ float ex2f(float x) {
    float y; asm("ex2.approx.ftz.f32 %0, %1;" : "=f"(y) : "f"(x)); return y;
}
__device__ __forceinline__ void cp_async16(uint32_t s, const void* g) {
    asm volatile("cp.async.cg.shared.global [%0], [%1], 16;" :: "r"(s), "l"(g));
}
__device__ __forceinline__ void cp_commit() { asm volatile("cp.async.commit_group;"); }

__device__ __forceinline__ void mma16816(float* d, const uint32_t* a, uint32_t b0, uint32_t b1) {
    asm volatile(
        "mma.sync.aligned.m16n8k16.row.col.f32.bf16.bf16.f32 "
        "{%0,%1,%2,%3}, {%4,%5,%6,%7}, {%8,%9}, {%0,%1,%2,%3};"
        : "+f"(d[0]), "+f"(d[1]), "+f"(d[2]), "+f"(d[3])
        : "r"(a[0]), "r"(a[1]), "r"(a[2]), "r"(a[3]), "r"(b0), "r"(b1));
}
__device__ __forceinline__ void ldsm4(uint32_t* r, uint32_t addr) {
    asm volatile("ldmatrix.sync.aligned.m8n8.x4.shared.b16 {%0,%1,%2,%3}, [%4];"
        : "=r"(r[0]), "=r"(r[1]), "=r"(r[2]), "=r"(r[3]) : "r"(addr));
}
__device__ __forceinline__ void ldsm4t(uint32_t* r, uint32_t addr) {
    asm volatile("ldmatrix.sync.aligned.m8n8.x4.trans.shared.b16 {%0,%1,%2,%3}, [%4];"
        : "=r"(r[0]), "=r"(r[1]), "=r"(r[2]), "=r"(r[3]) : "r"(addr));
}
__device__ __forceinline__ uint32_t packbf(float a, float b) {
    __nv_bfloat162 t = __floats2bfloat162_rn(a, b);
    return *reinterpret_cast<uint32_t*>(&t);
}

// ---------- kernel 1a: BN partial sums ----------
__global__ __launch_bounds__(256) void bn_part(const float* __restrict__ x) {
    int c = blockIdx.x >> 3, s = blockIdx.x & 7, t = threadIdx.x;
    const float* p = x + ((size_t)s * C + c) * HW;
    float sm = 0.f, sq = 0.f;
#pragma unroll
    for (int i = 0; i < HW / 256; i++) { float v = p[t + i * 256]; sm += v; sq += v * v; }
    __shared__ float rs[256], rq[256];
    rs[t] = sm; rq[t] = sq; __syncthreads();
    for (int o = 128; o > 0; o >>= 1) {
        if (t < o) { rs[t] += rs[t + o]; rq[t] += rq[t + o]; }
        __syncthreads();
    }
    if (t == 0) { g_ps[c * 8 + s] = rs[0]; g_pq[c * 8 + s] = rq[0]; }
}

// ---------- kernel 1b: BN finalize ----------
__global__ void bn_fin(const float* __restrict__ gamma, const float* __restrict__ beta) {
    int c = threadIdx.x;
    float sm = 0.f, sq = 0.f;
#pragma unroll
    for (int k = 0; k < 8; k++) { sm += g_ps[c * 8 + k]; sq += g_pq[c * 8 + k]; }
    float inv = 1.0f / (float)(NB * HW);
    float mean = sm * inv;
    float var = sq * inv - mean * mean;
    float sc = rsqrtf(var + EPS_BN) * gamma[c];
    g_scale[c] = sc;
    g_shift[c] = beta[c] - mean * sc;
}

// ---------- kernel 2: BN-apply + QKV via HMMA ----------
__global__ __launch_bounds__(128) void qkv_kernel(
    const float* __restrict__ x,
    const float* __restrict__ wq, const float* __restrict__ bq,
    const float* __restrict__ wk, const float* __restrict__ bk,
    const float* __restrict__ wv, const float* __restrict__ bv) {
    __shared__ __align__(16) char sX[128 * 128];
    __shared__ __align__(16) char sW[3][64 * 128];
    int t = threadIdx.x, wid = t >> 5, l = t & 31;
    int n = blockIdx.y;
    int p0 = blockIdx.x * 128;
    uint32_t sXa = smem_u32(sX);

    {
        const float* xb = x + (size_t)n * C * HW + p0 + t;
        int r7 = t & 7;
#pragma unroll
        for (int cp = 0; cp < 32; cp++) {
            int c0 = 2 * cp;
            float v0 = xb[(size_t)c0 * HW] * g_scale[c0] + g_shift[c0];
            float v1 = xb[(size_t)(c0 + 1) * HW] * g_scale[c0 + 1] + g_shift[c0 + 1];
            uint32_t pk = packbf(v0, v1);
            uint32_t off = ((uint32_t)(((c0 >> 3) ^ r7) << 4)) + (uint32_t)((c0 & 7) * 2);
            *reinterpret_cast<uint32_t*>(&((char*)sX)[t * 128 + off]) = pk;
        }
    }
    {
        const float* ws[3] = {wq, wk, wv};
#pragma unroll
        for (int w = 0; w < 3; w++) {
            const float* wp = ws[w];
#pragma unroll
            for (int i = 0; i < 16; i++) {
                int idx = t + i * 128;
                int o = idx >> 5, cp = idx & 31, c0 = 2 * cp;
                float2 wv2 = *reinterpret_cast<const float2*>(wp + o * 64 + c0);
                uint32_t pk = packbf(wv2.x, wv2.y);
                uint32_t off = ((uint32_t)(((c0 >> 3) ^ (o & 7)) << 4)) + (uint32_t)((c0 & 7) * 2);
                *reinterpret_cast<uint32_t*>(&sW[w][o * 128 + off]) = pk;
            }
        }
    }
    __syncthreads();

    uint32_t A[2][4][4];
    {
        int arow = (l & 7) + ((l >> 3) & 1) * 8;
        int l7 = l & 7;
#pragma unroll
        for (int mt2 = 0; mt2 < 2; mt2++) {
            int m0 = (wid * 2 + mt2) * 16;
#pragma unroll
            for (int kt = 0; kt < 4; kt++) {
                uint32_t chunk = (uint32_t)((kt * 2 + (l >> 4)) ^ l7);
                ldsm4(A[mt2][kt], sXa + (uint32_t)(m0 + arow) * 128 + (chunk << 4));
            }
        }
    }

    const float* biases[3] = {bq, bk, bv};
    __nv_bfloat16* outs[3] = {g_Q + (size_t)n * HW * C + (size_t)p0 * C,
                              g_Kb + (size_t)n * HW * C + (size_t)p0 * C,
                              g_V + (size_t)n * HW * C + (size_t)p0 * C};
    float scales[3] = {QSCALE, 1.f, 1.f};

    int brow = l & 7;
    uint32_t bx0 = (uint32_t)(((0 + (l >> 3)) ^ brow) << 4);
    uint32_t bx4 = (uint32_t)(((4 + (l >> 3)) ^ brow) << 4);

#pragma unroll
    for (int w = 0; w < 3; w++) {
        uint32_t sWa = smem_u32(sW[w]);
        float acc[2][8][4];
#pragma unroll
        for (int a = 0; a < 2; a++)
#pragma unroll
            for (int b = 0; b < 8; b++)
#pragma unroll
                for (int cc = 0; cc < 4; cc++) acc[a][b][cc] = 0.f;

#pragma unroll
        for (int nt = 0; nt < 8; nt++) {
            uint32_t base = sWa + (uint32_t)(nt * 8 + brow) * 128;
            uint32_t B[8];
            ldsm4(B, base + bx0);
            ldsm4(B + 4, base + bx4);
#pragma unroll
            for (int mt2 = 0; mt2 < 2; mt2++) {
                mma16816(acc[mt2][nt], A[mt2][0], B[0], B[1]);
                mma16816(acc[mt2][nt], A[mt2][1], B[2], B[3]);
                mma16816(acc[mt2][nt], A[mt2][2], B[4], B[5]);
                mma16816(acc[mt2][nt], A[mt2][3], B[6], B[7]);
            }
        }
        const float* bias = biases[w];
        float s = scales[w];
        __nv_bfloat16* op = outs[w];
#pragma unroll
        for (int nt = 0; nt < 8; nt++) {
            int col = nt * 8 + (l & 3) * 2;
            float2 bb = *reinterpret_cast<const float2*>(bias + col);
#pragma unroll
            for (int mt2 = 0; mt2 < 2; mt2++) {
                int row0 = (wid * 2 + mt2) * 16 + (l >> 2);
                uint32_t pk0 = packbf((acc[mt2][nt][0] + bb.x) * s, (acc[mt2][nt][1] + bb.y) * s);
                uint32_t pk1 = packbf((acc[mt2][nt][2] + bb.x) * s, (acc[mt2][nt][3] + bb.y) * s);
                *reinterpret_cast<uint32_t*>(op + (size_t)row0 * C + col) = pk0;
                *reinterpret_cast<uint32_t*>(op + (size_t)(row0 + 8) * C + col) = pk1;
            }
        }
    }
}

// ---------- kernel 3: flash attention, 32 q-rows per warp (2 mtiles, B-reuse) ----------
constexpr int ROWB = 144;

__global__ __launch_bounds__(128) void attn_kernel() {
    __shared__ __align__(16) char sK[2][KT * ROWB];  // [key][ch]
    __shared__ __align__(16) char sV[2][KT * ROWB];  // [key][ch]
    int t = threadIdx.x, wid = t >> 5, lane = t & 31;
    int n = blockIdx.y, qt = blockIdx.x;
    int qrow0 = qt * QT + wid * 32;        // warp owns 32 rows = 2 mtiles
    int m = lane >> 2;
    int qp = (lane & 3) * 2;

    const __nv_bfloat16* Kg = g_Kb + (size_t)n * HW * C;
    const __nv_bfloat16* Vg = g_V + (size_t)n * HW * C;

    uint32_t lds_off = (uint32_t)((lane & 7) * ROWB + (lane >> 3) * 16);
    uint32_t ldt_off = (uint32_t)(((lane & 7) + ((lane >> 3) & 1) * 8) * ROWB + (lane >> 4) * 16);
    uint32_t sKa = smem_u32(sK);
    uint32_t sVa = smem_u32(sV);

    // Q fragments (loop-invariant): 2 mtiles x 4 ksteps
    uint32_t qa[2][4][4];
#pragma unroll
    for (int mt = 0; mt < 2; mt++) {
        const __nv_bfloat16* Qb = g_Q + ((size_t)n * HW + qrow0 + mt * 16) * C;
#pragma unroll
        for (int kb = 0; kb < 4; kb++) {
            qa[mt][kb][0] = *(const uint32_t*)(Qb + (size_t)m * C + kb * 16 + qp);
            qa[mt][kb][1] = *(const uint32_t*)(Qb + (size_t)(m + 8) * C + kb * 16 + qp);
            qa[mt][kb][2] = *(const uint32_t*)(Qb + (size_t)m * C + kb * 16 + 8 + qp);
            qa[mt][kb][3] = *(const uint32_t*)(Qb + (size_t)(m + 8) * C + kb * 16 + 8 + qp);
        }
    }

    float oacc[2][8][4];
#pragma unroll
    for (int mt = 0; mt < 2; mt++)
#pragma unroll
        for (int i = 0; i < 8; i++)
#pragma unroll
            for (int j = 0; j < 4; j++) oacc[mt][i][j] = 0.f;
    float lsum[2][2] = {{0.f, 0.f}, {0.f, 0.f}};

    auto prefetch = [&](int b, int kt) {
#pragma unroll
        for (int rr = 0; rr < 4; rr++) {
            int ch = t + rr * 128;
            int row = ch >> 3, col = ch & 7;
            cp_async16(sKa + (uint32_t)(b * KT * ROWB + row * ROWB + col * 16),
                       Kg + ((size_t)(kt * KT + row)) * C + col * 8);
            cp_async16(sVa + (uint32_t)(b * KT * ROWB + row * ROWB + col * 16),
                       Vg + ((size_t)(kt * KT + row)) * C + col * 8);
        }
        cp_commit();
    };

    prefetch(0, 0);

    for (int kt = 0; kt < NKT; kt++) {
        asm volatile("cp.async.wait_group 0;");
        __syncthreads();
        if (kt + 1 < NKT) prefetch((kt + 1) & 1, kt + 1);

        uint32_t kb_a = sKa + (uint32_t)((kt & 1) * KT * ROWB) + lds_off;
        uint32_t vb_a = sVa + (uint32_t)((kt & 1) * KT * ROWB) + ldt_off;

        // MMA1 + softmax, processed in ntile pairs (kc = one k16 A-frag of P)
        uint32_t pa[2][4][4];
#pragma unroll
        for (int kc = 0; kc < 4; kc++) {
            float sacc[2][2][4];      // [mt][nt-in-pair][4]
#pragma unroll
            for (int j = 0; j < 2; j++) {
                int nt = kc * 2 + j;
                uint32_t B[8];
                ldsm4(B, kb_a + nt * 8 * ROWB);
                ldsm4(B + 4, kb_a + nt * 8 * ROWB + 64);
#pragma unroll
                for (int mt = 0; mt < 2; mt++) {
#pragma unroll
                    for (int z = 0; z < 4; z++) sacc[mt][j][z] = 0.f;
                    mma16816(sacc[mt][j], qa[mt][0], B[0], B[1]);
                    mma16816(sacc[mt][j], qa[mt][1], B[2], B[3]);
                    mma16816(sacc[mt][j], qa[mt][2], B[4], B[5]);
                    mma16816(sacc[mt][j], qa[mt][3], B[6], B[7]);
                }
            }
#pragma unroll
            for (int mt = 0; mt < 2; mt++) {
#pragma unroll
                for (int j = 0; j < 2; j++) {
                    float e0 = ex2f(sacc[mt][j][0]);
                    float e1 = ex2f(sacc[mt][j][1]);
                    float e2 = ex2f(sacc[mt][j][2]);
                    float e3 = ex2f(sacc[mt][j][3]);
                    lsum[mt][0] += e0 + e1;
                    lsum[mt][1] += e2 + e3;
                    pa[mt][kc][j * 2 + 0] = packbf(e0, e1);
                    pa[mt][kc][j * 2 + 1] = packbf(e2, e3);
                }
            }
        }

        // MMA2: O[32 x 64ch] += P * V, V frags shared across both mtiles
#pragma unroll
        for (int np = 0; np < 4; np++) {
#pragma unroll
            for (int kc = 0; kc < 4; kc++) {
                uint32_t B[4];
                ldsm4t(B, vb_a + (uint32_t)(kc * 16 * ROWB + np * 32));
#pragma unroll
                for (int mt = 0; mt < 2; mt++) {
                    mma16816(oacc[mt][2 * np], pa[mt][kc], B[0], B[1]);
                    mma16816(oacc[mt][2 * np + 1], pa[mt][kc], B[2], B[3]);
                }
            }
        }
    }

    // quad-reduce row sums and write out, per mtile
#pragma unroll
    for (int mt = 0; mt < 2; mt++) {
        float l0 = lsum[mt][0], l1 = lsum[mt][1];
        l0 += __shfl_xor_sync(0xffffffffu, l0, 1);
        l0 += __shfl_xor_sync(0xffffffffu, l0, 2);
        l1 += __shfl_xor_sync(0xffffffffu, l1, 1);
        l1 += __shfl_xor_sync(0xffffffffu, l1, 2);
        float inv0 = 1.f / l0, inv1 = 1.f / l1;

        float* orow0 = g_O + ((size_t)n * HW + qrow0 + mt * 16 + m) * C;
        float* orow1 = orow0 + 8 * C;
#pragma unroll
        for (int ct = 0; ct < 8; ct++) {
            int col = ct * 8 + qp;
            float2 v0 = make_float2(oacc[mt][ct][0] * inv0, oacc[mt][ct][1] * inv0);
            float2 v1 = make_float2(oacc[mt][ct][2] * inv1, oacc[mt][ct][3] * inv1);
            *reinterpret_cast<float2*>(orow0 + col) = v0;
            *reinterpret_cast<float2*>(orow1 + col) = v1;
        }
    }
}

// ---------- kernel 4: output conv + residual (R5 version) ----------
constexpr int OP = 64;
__global__ __launch_bounds__(256) void out_kernel(
    const float* __restrict__ x, const float* __restrict__ wo,
    const float* __restrict__ bo, float* __restrict__ out) {
    __shared__ float sW[C * C];
    __shared__ __align__(16) float sv[C][OP];
    int t = threadIdx.x;
    int n = blockIdx.y;
    int p0 = blockIdx.x * OP;
    int g = t >> 6, pl = t & 63, p = p0 + pl;

    float xv[16];
    const float* xb = x + (size_t)n * C * HW + p;
#pragma unroll
    for (int o = 0; o < 16; o++) xv[o] = xb[(size_t)(g * 16 + o) * HW];

    for (int j = t; j < C * C; j += 256) sW[(j & 63) * C + (j >> 6)] = wo[j];
    {
        const float* Ob = g_O + (size_t)n * C * HW + p0;
        for (int j = t; j < C * 16; j += 256) {
            int c = j >> 4, w = j & 15;
            float4 v = *reinterpret_cast<const float4*>(Ob + (size_t)c * HW + w * 4);
            *reinterpret_cast<float4*>(&sv[c][w * 4]) = v;
        }
    }
    __syncthreads();

    float acc[16];
#pragma unroll
    for (int o = 0; o < 16; o++) acc[o] = bo[g * 16 + o];
#pragma unroll
    for (int c = 0; c < C; c++) {
        float v = sv[c][pl];
#pragma unroll
        for (int o = 0; o < 16; o++) acc[o] += sW[c * C + g * 16 + o] * v;
    }
    float* ob = out + (size_t)n * C * HW + p;
#pragma unroll
    for (int o = 0; o < 16; o++)
        ob[(size_t)(g * 16 + o) * HW] = acc[o] + xv[o];
}

extern "C" void kernel_launch(void* const* d_in, const int* in_sizes, int n_in,
                              void* d_out, int out_size) {
    const float* x     = (const float*)d_in[0];
    const float* gamma = (const float*)d_in[1];
    const float* beta  = (const float*)d_in[2];
    const float* wq    = (const float*)d_in[3];
    const float* bq    = (const float*)d_in[4];
    const float* wk    = (const float*)d_in[5];
    const float* bk    = (const float*)d_in[6];
    const float* wv    = (const float*)d_in[7];
    const float* bv    = (const float*)d_in[8];
    const float* wo    = (const float*)d_in[9];
    const float* bo    = (const float*)d_in[10];
    float* out = (float*)d_out;

    bn_part<<<512, 256>>>(x);
    bn_fin<<<1, 64>>>(gamma, beta);
    qkv_kernel<<<dim3(HW / 128, NB), 128>>>(x, wq, bq, wk, bk, wv, bv);
    attn_kernel<<<dim3(HW / QT, NB), 128>>>();
    out_kernel<<<dim3(HW / OP, NB), 256>>>(x, wo, bo, out);
}

// round 11
// speedup vs baseline: 1.7296x; 1.0002x over previous
#include <cuda_runtime.h>
#include <cuda_bf16.h>
#include <cstdint>

constexpr int NB = 8, C = 64, HW = 4096;
constexpr int QT = 128;                // q rows per CTA (32 per warp, 2 mtiles)
constexpr int KT = 64;                 // keys per iteration tile
constexpr int NKT = HW / KT;           // 64
constexpr float EPS_BN = 1e-5f;
constexpr float QSCALE = 0.125f * 1.4426950408889634f;  // (1/sqrt(64)) * log2(e)

__device__ __align__(256) float g_scale[C];
__device__ __align__(256) float g_shift[C];
__device__ __align__(256) float g_ps[512];
__device__ __align__(256) float g_pq[512];
__device__ __align__(256) __nv_bfloat16 g_Q[(size_t)NB * HW * C];   // [n,i,c] pre-scaled
__device__ __align__(256) __nv_bfloat16 g_Kb[(size_t)NB * HW * C];  // [n,j,c]
__device__ __align__(256) __nv_bfloat16 g_V[(size_t)NB * HW * C];   // [n,j,c]
__device__ __align__(256) float g_O[(size_t)NB * HW * C];           // [n,i,c]

// ---------- helpers ----------
__device__ __forceinline__ uint32_t smem_u32(const void* p) {
    uint32_t a;
    asm("{ .reg .u64 t; cvta.to.shared.u64 t, %1; cvt.u32.u64 %0, t; }" : "=r"(a) : "l"(p));
    return a;
}
__device__ __forceinline__ float ex2f(float x) {
    float y; asm("ex2.approx.ftz.f32 %0, %1;" : "=f"(y) : "f"(x)); return y;
}
__device__ __forceinline__ void cp_async16(uint32_t s, const void* g) {
    asm volatile("cp.async.cg.shared.global [%0], [%1], 16;" :: "r"(s), "l"(g));
}
__device__ __forceinline__ void cp_commit() { asm volatile("cp.async.commit_group;"); }

__device__ __forceinline__ void mma16816(float* d, const uint32_t* a, uint32_t b0, uint32_t b1) {
    asm volatile(
        "mma.sync.aligned.m16n8k16.row.col.f32.bf16.bf16.f32 "
        "{%0,%1,%2,%3}, {%4,%5,%6,%7}, {%8,%9}, {%0,%1,%2,%3};"
        : "+f"(d[0]), "+f"(d[1]), "+f"(d[2]), "+f"(d[3])
        : "r"(a[0]), "r"(a[1]), "r"(a[2]), "r"(a[3]), "r"(b0), "r"(b1));
}
__device__ __forceinline__ void ldsm4(uint32_t* r, uint32_t addr) {
    asm volatile("ldmatrix.sync.aligned.m8n8.x4.shared.b16 {%0,%1,%2,%3}, [%4];"
        : "=r"(r[0]), "=r"(r[1]), "=r"(r[2]), "=r"(r[3]) : "r"(addr));
}
__device__ __forceinline__ void ldsm4t(uint32_t* r, uint32_t addr) {
    asm volatile("ldmatrix.sync.aligned.m8n8.x4.trans.shared.b16 {%0,%1,%2,%3}, [%4];"
        : "=r"(r[0]), "=r"(r[1]), "=r"(r[2]), "=r"(r[3]) : "r"(addr));
}
__device__ __forceinline__ uint32_t packbf(float a, float b) {
    __nv_bfloat162 t = __floats2bfloat162_rn(a, b);
    return *reinterpret_cast<uint32_t*>(&t);
}

// ---------- kernel 1a: BN partial sums ----------
__global__ __launch_bounds__(256) void bn_part(const float* __restrict__ x) {
    int c = blockIdx.x >> 3, s = blockIdx.x & 7, t = threadIdx.x;
    const float* p = x + ((size_t)s * C + c) * HW;
    float sm = 0.f, sq = 0.f;
#pragma unroll
    for (int i = 0; i < HW / 256; i++) { float v = p[t + i * 256]; sm += v; sq += v * v; }
    __shared__ float rs[256], rq[256];
    rs[t] = sm; rq[t] = sq; __syncthreads();
    for (int o = 128; o > 0; o >>= 1) {
        if (t < o) { rs[t] += rs[t + o]; rq[t] += rq[t + o]; }
        __syncthreads();
    }
    if (t == 0) { g_ps[c * 8 + s] = rs[0]; g_pq[c * 8 + s] = rq[0]; }
}

// ---------- kernel 1b: BN finalize ----------
__global__ void bn_fin(const float* __restrict__ gamma, const float* __restrict__ beta) {
    int c = threadIdx.x;
    float sm = 0.f, sq = 0.f;
#pragma unroll
    for (int k = 0; k < 8; k++) { sm += g_ps[c * 8 + k]; sq += g_pq[c * 8 + k]; }
    float inv = 1.0f / (float)(NB * HW);
    float mean = sm * inv;
    float var = sq * inv - mean * mean;
    float sc = rsqrtf(var + EPS_BN) * gamma[c];
    g_scale[c] = sc;
    g_shift[c] = beta[c] - mean * sc;
}

// ---------- kernel 2: BN-apply + QKV via HMMA ----------
__global__ __launch_bounds__(128) void qkv_kernel(
    const float* __restrict__ x,
    const float* __restrict__ wq, const float* __restrict__ bq,
    const float* __restrict__ wk, const float* __restrict__ bk,
    const float* __restrict__ wv, const float* __restrict__ bv) {
    __shared__ __align__(16) char sX[128 * 128];
    __shared__ __align__(16) char sW[3][64 * 128];
    int t = threadIdx.x, wid = t >> 5, l = t & 31;
    int n = blockIdx.y;
    int p0 = blockIdx.x * 128;
    uint32_t sXa = smem_u32(sX);

    {
        const float* xb = x + (size_t)n * C * HW + p0 + t;
        int r7 = t & 7;
#pragma unroll
        for (int cp = 0; cp < 32; cp++) {
            int c0 = 2 * cp;
            float v0 = xb[(size_t)c0 * HW] * g_scale[c0] + g_shift[c0];
            float v1 = xb[(size_t)(c0 + 1) * HW] * g_scale[c0 + 1] + g_shift[c0 + 1];
            uint32_t pk = packbf(v0, v1);
            uint32_t off = ((uint32_t)(((c0 >> 3) ^ r7) << 4)) + (uint32_t)((c0 & 7) * 2);
            *reinterpret_cast<uint32_t*>(&((char*)sX)[t * 128 + off]) = pk;
        }
    }
    {
        const float* ws[3] = {wq, wk, wv};
#pragma unroll
        for (int w = 0; w < 3; w++) {
            const float* wp = ws[w];
#pragma unroll
            for (int i = 0; i < 16; i++) {
                int idx = t + i * 128;
                int o = idx >> 5, cp = idx & 31, c0 = 2 * cp;
                float2 wv2 = *reinterpret_cast<const float2*>(wp + o * 64 + c0);
                uint32_t pk = packbf(wv2.x, wv2.y);
                uint32_t off = ((uint32_t)(((c0 >> 3) ^ (o & 7)) << 4)) + (uint32_t)((c0 & 7) * 2);
                *reinterpret_cast<uint32_t*>(&sW[w][o * 128 + off]) = pk;
            }
        }
    }
    __syncthreads();

    uint32_t A[2][4][4];
    {
        int arow = (l & 7) + ((l >> 3) & 1) * 8;
        int l7 = l & 7;
#pragma unroll
        for (int mt2 = 0; mt2 < 2; mt2++) {
            int m0 = (wid * 2 + mt2) * 16;
#pragma unroll
            for (int kt = 0; kt < 4; kt++) {
                uint32_t chunk = (uint32_t)((kt * 2 + (l >> 4)) ^ l7);
                ldsm4(A[mt2][kt], sXa + (uint32_t)(m0 + arow) * 128 + (chunk << 4));
            }
        }
    }

    const float* biases[3] = {bq, bk, bv};
    __nv_bfloat16* outs[3] = {g_Q + (size_t)n * HW * C + (size_t)p0 * C,
                              g_Kb + (size_t)n * HW * C + (size_t)p0 * C,
                              g_V + (size_t)n * HW * C + (size_t)p0 * C};
    float scales[3] = {QSCALE, 1.f, 1.f};

    int brow = l & 7;
    uint32_t bx0 = (uint32_t)(((0 + (l >> 3)) ^ brow) << 4);
    uint32_t bx4 = (uint32_t)(((4 + (l >> 3)) ^ brow) << 4);

#pragma unroll
    for (int w = 0; w < 3; w++) {
        uint32_t sWa = smem_u32(sW[w]);
        float acc[2][8][4];
#pragma unroll
        for (int a = 0; a < 2; a++)
#pragma unroll
            for (int b = 0; b < 8; b++)
#pragma unroll
                for (int cc = 0; cc < 4; cc++) acc[a][b][cc] = 0.f;

#pragma unroll
        for (int nt = 0; nt < 8; nt++) {
            uint32_t base = sWa + (uint32_t)(nt * 8 + brow) * 128;
            uint32_t B[8];
            ldsm4(B, base + bx0);
            ldsm4(B + 4, base + bx4);
#pragma unroll
            for (int mt2 = 0; mt2 < 2; mt2++) {
                mma16816(acc[mt2][nt], A[mt2][0], B[0], B[1]);
                mma16816(acc[mt2][nt], A[mt2][1], B[2], B[3]);
                mma16816(acc[mt2][nt], A[mt2][2], B[4], B[5]);
                mma16816(acc[mt2][nt], A[mt2][3], B[6], B[7]);
            }
        }
        const float* bias = biases[w];
        float s = scales[w];
        __nv_bfloat16* op = outs[w];
#pragma unroll
        for (int nt = 0; nt < 8; nt++) {
            int col = nt * 8 + (l & 3) * 2;
            float2 bb = *reinterpret_cast<const float2*>(bias + col);
#pragma unroll
            for (int mt2 = 0; mt2 < 2; mt2++) {
                int row0 = (wid * 2 + mt2) * 16 + (l >> 2);
                uint32_t pk0 = packbf((acc[mt2][nt][0] + bb.x) * s, (acc[mt2][nt][1] + bb.y) * s);
                uint32_t pk1 = packbf((acc[mt2][nt][2] + bb.x) * s, (acc[mt2][nt][3] + bb.y) * s);
                *reinterpret_cast<uint32_t*>(op + (size_t)row0 * C + col) = pk0;
                *reinterpret_cast<uint32_t*>(op + (size_t)(row0 + 8) * C + col) = pk1;
            }
        }
    }
}

// ---------- kernel 3: flash attention, 6-buffer ring, 1 barrier / 2 iters ----------
constexpr int ROWB = 144;
constexpr int TILE_B = KT * ROWB;          // 9216 bytes
constexpr int NBUF = 6;
constexpr int ATTN_SMEM = 2 * NBUF * TILE_B;   // 110592 bytes

__global__ __launch_bounds__(128) void attn_kernel() {
    extern __shared__ __align__(16) char smem[];
    int t = threadIdx.x, wid = t >> 5, lane = t & 31;
    int n = blockIdx.y, qt = blockIdx.x;
    int qrow0 = qt * QT + wid * 32;        // warp owns 32 rows = 2 mtiles
    int m = lane >> 2;
    int qp = (lane & 3) * 2;

    const __nv_bfloat16* Kg = g_Kb + (size_t)n * HW * C;
    const __nv_bfloat16* Vg = g_V + (size_t)n * HW * C;

    uint32_t lds_off = (uint32_t)((lane & 7) * ROWB + (lane >> 3) * 16);
    uint32_t ldt_off = (uint32_t)(((lane & 7) + ((lane >> 3) & 1) * 8) * ROWB + (lane >> 4) * 16);
    uint32_t sKa = smem_u32(smem);                       // 6 K buffers
    uint32_t sVa = sKa + (uint32_t)(NBUF * TILE_B);      // 6 V buffers

    // Q fragments (loop-invariant): 2 mtiles x 4 ksteps
    uint32_t qa[2][4][4];
#pragma unroll
    for (int mt = 0; mt < 2; mt++) {
        const __nv_bfloat16* Qb = g_Q + ((size_t)n * HW + qrow0 + mt * 16) * C;
#pragma unroll
        for (int kb = 0; kb < 4; kb++) {
            qa[mt][kb][0] = *(const uint32_t*)(Qb + (size_t)m * C + kb * 16 + qp);
            qa[mt][kb][1] = *(const uint32_t*)(Qb + (size_t)(m + 8) * C + kb * 16 + qp);
            qa[mt][kb][2] = *(const uint32_t*)(Qb + (size_t)m * C + kb * 16 + 8 + qp);
            qa[mt][kb][3] = *(const uint32_t*)(Qb + (size_t)(m + 8) * C + kb * 16 + 8 + qp);
        }
    }

    float oacc[2][8][4];
#pragma unroll
    for (int mt = 0; mt < 2; mt++)
#pragma unroll
        for (int i = 0; i < 8; i++)
#pragma unroll
            for (int j = 0; j < 4; j++) oacc[mt][i][j] = 0.f;
    float lsum[2][2] = {{0.f, 0.f}, {0.f, 0.f}};

    // prefetch tile kt into ring buffer kt % NBUF; always commits (group counting)
    auto prefetch = [&](int kt) {
        if (kt < NKT) {
            uint32_t b = (uint32_t)(kt % NBUF) * TILE_B;
#pragma unroll
            for (int rr = 0; rr < 4; rr++) {
                int ch = t + rr * 128;
                int row = ch >> 3, col = ch & 7;
                cp_async16(sKa + b + (uint32_t)(row * ROWB + col * 16),
                           Kg + ((size_t)(kt * KT + row)) * C + col * 8);
                cp_async16(sVa + b + (uint32_t)(row * ROWB + col * 16),
                           Vg + ((size_t)(kt * KT + row)) * C + col * 8);
            }
        }
        cp_commit();
    };

    // prologue: tiles 0..3 in flight (4 groups)
    prefetch(0); prefetch(1); prefetch(2); prefetch(3);

    for (int s = 0; s < NKT; s += 2) {
        // tiles s, s+1 ready when only the 2 newest groups may be outstanding
        asm volatile("cp.async.wait_group 2;");
        __syncthreads();   // visibility of tiles s,s+1 + reuse-protection for upcoming prefetch

#pragma unroll
        for (int u = 0; u < 2; u++) {
            int kt = s + u;
            uint32_t b = (uint32_t)(kt % NBUF) * TILE_B;
            uint32_t kb_a = sKa + b + lds_off;
            uint32_t vb_a = sVa + b + ldt_off;

            // MMA1 + softmax, in ntile pairs (kc = one k16 A-frag of P)
            uint32_t pa[2][4][4];
#pragma unroll
            for (int kc = 0; kc < 4; kc++) {
                float sacc[2][2][4];
#pragma unroll
                for (int j = 0; j < 2; j++) {
                    int nt = kc * 2 + j;
                    uint32_t B[8];
                    ldsm4(B, kb_a + nt * 8 * ROWB);
                    ldsm4(B + 4, kb_a + nt * 8 * ROWB + 64);
#pragma unroll
                    for (int mt = 0; mt < 2; mt++) {
#pragma unroll
                        for (int z = 0; z < 4; z++) sacc[mt][j][z] = 0.f;
                        mma16816(sacc[mt][j], qa[mt][0], B[0], B[1]);
                        mma16816(sacc[mt][j], qa[mt][1], B[2], B[3]);
                        mma16816(sacc[mt][j], qa[mt][2], B[4], B[5]);
                        mma16816(sacc[mt][j], qa[mt][3], B[6], B[7]);
                    }
                }
#pragma unroll
                for (int mt = 0; mt < 2; mt++) {
#pragma unroll
                    for (int j = 0; j < 2; j++) {
                        float e0 = ex2f(sacc[mt][j][0]);
                        float e1 = ex2f(sacc[mt][j][1]);
                        float e2 = ex2f(sacc[mt][j][2]);
                        float e3 = ex2f(sacc[mt][j][3]);
                        lsum[mt][0] += e0 + e1;
                        lsum[mt][1] += e2 + e3;
                        pa[mt][kc][j * 2 + 0] = packbf(e0, e1);
                        pa[mt][kc][j * 2 + 1] = packbf(e2, e3);
                    }
                }
            }

            // MMA2: O += P * V, V frags shared across both mtiles
#pragma unroll
            for (int np = 0; np < 4; np++) {
#pragma unroll
                for (int kc = 0; kc < 4; kc++) {
                    uint32_t B[4];
                    ldsm4t(B, vb_a + (uint32_t)(kc * 16 * ROWB + np * 32));
#pragma unroll
                    for (int mt = 0; mt < 2; mt++) {
                        mma16816(oacc[mt][2 * np], pa[mt][kc], B[0], B[1]);
                        mma16816(oacc[mt][2 * np + 1], pa[mt][kc], B[2], B[3]);
                    }
                }
            }
        }

        // prefetch next window's +2 tiles (buffers last read 2 windows ago — safe
        // because every warp passed this window's barrier before any prefetch here)
        prefetch(s + 4);
        prefetch(s + 5);
    }

#pragma unroll
    for (int mt = 0; mt < 2; mt++) {
        float l0 = lsum[mt][0], l1 = lsum[mt][1];
        l0 += __shfl_xor_sync(0xffffffffu, l0, 1);
        l0 += __shfl_xor_sync(0xffffffffu, l0, 2);
        l1 += __shfl_xor_sync(0xffffffffu, l1, 1);
        l1 += __shfl_xor_sync(0xffffffffu, l1, 2);
        float inv0 = 1.f / l0, inv1 = 1.f / l1;

        float* orow0 = g_O + ((size_t)n * HW + qrow0 + mt * 16 + m) * C;
        float* orow1 = orow0 + 8 * C;
#pragma unroll
        for (int ct = 0; ct < 8; ct++) {
            int col = ct * 8 + qp;
            float2 v0 = make_float2(oacc[mt][ct][0] * inv0, oacc[mt][ct][1] * inv0);
            float2 v1 = make_float2(oacc[mt][ct][2] * inv1, oacc[mt][ct][3] * inv1);
            *reinterpret_cast<float2*>(orow0 + col) = v0;
            *reinterpret_cast<float2*>(orow1 + col) = v1;
        }
    }
}

// ---------- kernel 4: output conv + residual (R5 version) ----------
constexpr int OP = 64;
__global__ __launch_bounds__(256) void out_kernel(
    const float* __restrict__ x, const float* __restrict__ wo,
    const float* __restrict__ bo, float* __restrict__ out) {
    __shared__ float sW[C * C];
    __shared__ __align__(16) float sv[C][OP];
    int t = threadIdx.x;
    int n = blockIdx.y;
    int p0 = blockIdx.x * OP;
    int g = t >> 6, pl = t & 63, p = p0 + pl;

    float xv[16];
    const float* xb = x + (size_t)n * C * HW + p;
#pragma unroll
    for (int o = 0; o < 16; o++) xv[o] = xb[(size_t)(g * 16 + o) * HW];

    for (int j = t; j < C * C; j += 256) sW[(j & 63) * C + (j >> 6)] = wo[j];
    {
        const float* Ob = g_O + (size_t)n * C * HW + p0;
        for (int j = t; j < C * 16; j += 256) {
            int c = j >> 4, w = j & 15;
            float4 v = *reinterpret_cast<const float4*>(Ob + (size_t)c * HW + w * 4);
            *reinterpret_cast<float4*>(&sv[c][w * 4]) = v;
        }
    }
    __syncthreads();

    float acc[16];
#pragma unroll
    for (int o = 0; o < 16; o++) acc[o] = bo[g * 16 + o];
#pragma unroll
    for (int c = 0; c < C; c++) {
        float v = sv[c][pl];
#pragma unroll
        for (int o = 0; o < 16; o++) acc[o] += sW[c * C + g * 16 + o] * v;
    }
    float* ob = out + (size_t)n * C * HW + p;
#pragma unroll
    for (int o = 0; o < 16; o++)
        ob[(size_t)(g * 16 + o) * HW] = acc[o] + xv[o];
}

extern "C" void kernel_launch(void* const* d_in, const int* in_sizes, int n_in,
                              void* d_out, int out_size) {
    const float* x     = (const float*)d_in[0];
    const float* gamma = (const float*)d_in[1];
    const float* beta  = (const float*)d_in[2];
    const float* wq    = (const float*)d_in[3];
    const float* bq    = (const float*)d_in[4];
    const float* wk    = (const float*)d_in[5];
    const float* bk    = (const float*)d_in[6];
    const float* wv    = (const float*)d_in[7];
    const float* bv    = (const float*)d_in[8];
    const float* wo    = (const float*)d_in[9];
    const float* bo    = (const float*)d_in[10];
    float* out = (float*)d_out;

    cudaFuncSetAttribute(attn_kernel, cudaFuncAttributeMaxDynamicSharedMemorySize, ATTN_SMEM);

    bn_part<<<512, 256>>>(x);
    bn_fin<<<1, 64>>>(gamma, beta);
    qkv_kernel<<<dim3(HW / 128, NB), 128>>>(x, wq, bq, wk, bk, wv, bv);
    attn_kernel<<<dim3(HW / QT, NB), 128, ATTN_SMEM>>>();
    out_kernel<<<dim3(HW / OP, NB), 256>>>(x, wo, bo, out);
}